// round 16
// baseline (speedup 1.0000x reference)
#include <cuda_runtime.h>
#include <cuda_fp16.h>
#include <cstdint>

#define NG 4000      // genomes
#define NS 2048      // samples
#define NM 28000     // genes
#define NK 16000     // unique seqs
#define CAP 24       // max genes per seq bucket
#define HALF_S 1024  // sample half-width

// Scratch (allocation-free: __device__ globals; zero-initialized at load)
__device__ int    k_cnt[NK];                // bucket cursors (0 at entry & exit of every launch)
__device__ float2 k_slot[(size_t)NK * CAP]; // per-seq bucket: .x = genome idx (bits), .y = pos
__device__ __half Bh[(size_t)NG * NS];      // B in fp16, 16 MB

__device__ __forceinline__ float ex2f(float x) {
    float y;
    asm("ex2.approx.ftz.f32 %0, %1;" : "=f"(y) : "f"(x));
    return y;
}
__device__ __forceinline__ unsigned h2_as_u32(__half2 h) {
    union { __half2 h; unsigned u; } c; c.h = h; return c.u;
}
__device__ __forceinline__ float2 u32_as_f2h(unsigned u) {
    union { unsigned u; __half2 h; } c; c.u = u; return __half22float2(c.h);
}

struct f8 { float v[8]; };

// 32B A row load: non-coherent, pin in L2 (evict_last).
__device__ __forceinline__ f8 ldg_el8(const float* p) {
    unsigned r0, r1, r2, r3, r4, r5, r6, r7;
    asm("ld.global.nc.L2::evict_last.v8.b32 {%0,%1,%2,%3,%4,%5,%6,%7}, [%8];"
        : "=r"(r0), "=r"(r1), "=r"(r2), "=r"(r3),
          "=r"(r4), "=r"(r5), "=r"(r6), "=r"(r7) : "l"(p));
    f8 o;
    o.v[0] = __uint_as_float(r0); o.v[1] = __uint_as_float(r1);
    o.v[2] = __uint_as_float(r2); o.v[3] = __uint_as_float(r3);
    o.v[4] = __uint_as_float(r4); o.v[5] = __uint_as_float(r5);
    o.v[6] = __uint_as_float(r6); o.v[7] = __uint_as_float(r7);
    return o;
}

// 16B non-coherent load: 8 fp16 B samples.
__device__ __forceinline__ uint4 ldg_nc4(const void* p) {
    uint4 v;
    asm("ld.global.nc.v4.b32 {%0,%1,%2,%3}, [%4];"
        : "=r"(v.x), "=r"(v.y), "=r"(v.z), "=r"(v.w) : "l"(p));
    return v;
}

// Output stores: streaming (evict-first) so the 128MB stream never displaces A/Bh in L2.
__device__ __forceinline__ void stg_cs4(float* p, float a, float b, float c, float d) {
    asm volatile("st.global.cs.v4.f32 [%0], {%1,%2,%3,%4};"
                 :: "l"(p), "f"(a), "f"(b), "f"(c), "f"(d) : "memory");
}

// ---- Conversion kernel: one sample-half of B -> fp16. grid: NG*HALF_S/8 threads. ----
// do_scatter=1 variant (lo half) also does the bucket scatter in its first NM threads.
// Fires the PDL trigger immediately so a programmatic-launch successor can overlap.
__global__ void __launch_bounds__(256)
conv_kernel(const float* __restrict__ B, int col_base, int do_scatter,
            const int* __restrict__ genome_idx, const int* __restrict__ seq_idx,
            const float* __restrict__ pos) {
    asm volatile("griddepcontrol.launch_dependents;" ::: "memory");
    const int i = blockIdx.x * blockDim.x + threadIdx.x;   // 0 .. NG*HALF_S/8-1
    const int r = i >> 7;                                  // 128 threads per row-half
    const int c = ((i & 127) << 3) + col_base;
    const size_t idx = (size_t)r * NS + c;
    const float4 x = __ldg(reinterpret_cast<const float4*>(B + idx));
    const float4 y = __ldg(reinterpret_cast<const float4*>(B + idx) + 1);
    uint4 packed;
    packed.x = h2_as_u32(__floats2half2_rn(x.x, x.y));
    packed.y = h2_as_u32(__floats2half2_rn(x.z, x.w));
    packed.z = h2_as_u32(__floats2half2_rn(y.x, y.y));
    packed.w = h2_as_u32(__floats2half2_rn(y.z, y.w));
    *reinterpret_cast<uint4*>(Bh + idx) = packed;

    if (do_scatter && i < NM) {                            // bucket scatter (k_cnt: 0 -> cnt)
        int k = seq_idx[i];
        int cur = atomicAdd(&k_cnt[k], 1);
        if (cur < CAP) {
            float2 payload;
            payload.x = __int_as_float(genome_idx[i]);
            payload.y = pos[i];
            k_slot[(size_t)k * CAP + cur] = payload;
        }
    }
}

// ---- Main: seq-major fused gather over one sample half (A fp32 + B fp16). ----
// grid: NK CTAs; 128 threads; each thread owns 8 consecutive samples (128*8 == HALF_S).
__global__ void __launch_bounds__(128, 12)
main_kernel(const float* __restrict__ A, const float* __restrict__ bias,
            float* __restrict__ out, int s_base, int do_reset) {
    const int k  = blockIdx.x;                  // output seq row
    const int s0 = s_base + threadIdx.x * 8;

    int cnt = k_cnt[k];
    if (cnt > CAP) cnt = CAP;
    const float2* slots = k_slot + (size_t)k * CAP;

    // G = A * 2^(1 - p*B) = 2 * A * 2^(-p*B): fold the 2 into bias.
    const float w = 2.0f * __ldg(bias + k);

    float acc[8];
#pragma unroll
    for (int j = 0; j < 8; j++) acc[j] = 0.f;

    // Software-pipelined slot payloads (proven in R13).
    float2 p0, p1;
    if (cnt > 0) p0 = slots[0];
    if (cnt > 1) p1 = slots[1];

    int i = 0;
    for (; i + 2 <= cnt; i += 2) {
        const float2 c0 = p0;
        const float2 c1 = p1;
        if (i + 3 < cnt) { p0 = slots[i + 2]; p1 = slots[i + 3]; }
        else if (i + 2 < cnt) { p0 = slots[i + 2]; }

        const size_t n0 = (size_t)__float_as_int(c0.x) * NS + s0;
        const size_t n1 = (size_t)__float_as_int(c1.x) * NS + s0;
        const f8   a0 = ldg_el8(A + n0);
        const uint4 h0 = ldg_nc4(Bh + n0);
        const f8   a1 = ldg_el8(A + n1);
        const uint4 h1 = ldg_nc4(Bh + n1);
        {
            const float2 b01 = u32_as_f2h(h0.x), b23 = u32_as_f2h(h0.y);
            const float2 b45 = u32_as_f2h(h0.z), b67 = u32_as_f2h(h0.w);
            acc[0] = fmaf(a0.v[0], ex2f(-c0.y * b01.x), acc[0]);
            acc[1] = fmaf(a0.v[1], ex2f(-c0.y * b01.y), acc[1]);
            acc[2] = fmaf(a0.v[2], ex2f(-c0.y * b23.x), acc[2]);
            acc[3] = fmaf(a0.v[3], ex2f(-c0.y * b23.y), acc[3]);
            acc[4] = fmaf(a0.v[4], ex2f(-c0.y * b45.x), acc[4]);
            acc[5] = fmaf(a0.v[5], ex2f(-c0.y * b45.y), acc[5]);
            acc[6] = fmaf(a0.v[6], ex2f(-c0.y * b67.x), acc[6]);
            acc[7] = fmaf(a0.v[7], ex2f(-c0.y * b67.y), acc[7]);
        }
        {
            const float2 b01 = u32_as_f2h(h1.x), b23 = u32_as_f2h(h1.y);
            const float2 b45 = u32_as_f2h(h1.z), b67 = u32_as_f2h(h1.w);
            acc[0] = fmaf(a1.v[0], ex2f(-c1.y * b01.x), acc[0]);
            acc[1] = fmaf(a1.v[1], ex2f(-c1.y * b01.y), acc[1]);
            acc[2] = fmaf(a1.v[2], ex2f(-c1.y * b23.x), acc[2]);
            acc[3] = fmaf(a1.v[3], ex2f(-c1.y * b23.y), acc[3]);
            acc[4] = fmaf(a1.v[4], ex2f(-c1.y * b45.x), acc[4]);
            acc[5] = fmaf(a1.v[5], ex2f(-c1.y * b45.y), acc[5]);
            acc[6] = fmaf(a1.v[6], ex2f(-c1.y * b67.x), acc[6]);
            acc[7] = fmaf(a1.v[7], ex2f(-c1.y * b67.y), acc[7]);
        }
    }
    if (i < cnt) {
        const size_t n0 = (size_t)__float_as_int(p0.x) * NS + s0;
        const f8   a0 = ldg_el8(A + n0);
        const uint4 h0 = ldg_nc4(Bh + n0);
        const float2 b01 = u32_as_f2h(h0.x), b23 = u32_as_f2h(h0.y);
        const float2 b45 = u32_as_f2h(h0.z), b67 = u32_as_f2h(h0.w);
        acc[0] = fmaf(a0.v[0], ex2f(-p0.y * b01.x), acc[0]);
        acc[1] = fmaf(a0.v[1], ex2f(-p0.y * b01.y), acc[1]);
        acc[2] = fmaf(a0.v[2], ex2f(-p0.y * b23.x), acc[2]);
        acc[3] = fmaf(a0.v[3], ex2f(-p0.y * b23.y), acc[3]);
        acc[4] = fmaf(a0.v[4], ex2f(-p0.y * b45.x), acc[4]);
        acc[5] = fmaf(a0.v[5], ex2f(-p0.y * b45.y), acc[5]);
        acc[6] = fmaf(a0.v[6], ex2f(-p0.y * b67.x), acc[6]);
        acc[7] = fmaf(a0.v[7], ex2f(-p0.y * b67.y), acc[7]);
    }

    float* po = out + (size_t)k * NS + s0;
    stg_cs4(po,     w * acc[0], w * acc[1], w * acc[2], w * acc[3]);
    stg_cs4(po + 4, w * acc[4], w * acc[5], w * acc[6], w * acc[7]);

    // Only the LAST consumer of k_cnt may reset it (main_hi).
    if (do_reset && threadIdx.x == 0) k_cnt[k] = 0;
}

// ---------------- launch ----------------
extern "C" void kernel_launch(void* const* d_in, const int* in_sizes, int n_in,
                              void* d_out, int out_size) {
    const float* A          = (const float*)d_in[0];   // (4000, 2048)
    const float* B          = (const float*)d_in[1];   // (4000, 2048)
    const float* bias       = (const float*)d_in[2];   // (16000,)
    const float* pos        = (const float*)d_in[3];   // (28000,)
    const int*   genome_idx = (const int*)d_in[4];     // (28000,)
    const int*   seq_idx    = (const int*)d_in[5];     // (28000,)
    float*       out        = (float*)d_out;           // (16000, 2048)

    const int conv_blocks = (NG * HALF_S / 8) / 256;   // 2000

    // 1. prep_lo: convert B[:, 0:1024) + bucket scatter.
    conv_kernel<<<conv_blocks, 256>>>(B, 0, 1, genome_idx, seq_idx, pos);

    // 2. conv_hi: convert B[:, 1024:2048). Fires PDL trigger at entry.
    conv_kernel<<<conv_blocks, 256>>>(B, HALF_S, 0, genome_idx, seq_idx, pos);

    // 3. main_lo (samples 0-1023): programmatic launch — overlaps conv_hi.
    //    Safe: reads only Bh-low (from completed prep_lo); conv_hi writes Bh-high.
    {
        cudaLaunchConfig_t cfg = {};
        cfg.gridDim  = dim3(NK);
        cfg.blockDim = dim3(128);
        cfg.dynamicSmemBytes = 0;
        cfg.stream = 0;
        cudaLaunchAttribute attrs[1];
        attrs[0].id = cudaLaunchAttributeProgrammaticStreamSerialization;
        attrs[0].val.programmaticStreamSerializationAllowed = 1;
        cfg.attrs = attrs;
        cfg.numAttrs = 1;
        cudaLaunchKernelEx(&cfg, main_kernel, A, bias, out, 0, 0);
    }

    // 4. main_hi (samples 1024-2047): normal launch (waits all prior), resets k_cnt.
    main_kernel<<<NK, 128>>>(A, bias, out, HALF_S, 1);
}

// round 17
// speedup vs baseline: 1.0572x; 1.0572x over previous
#include <cuda_runtime.h>
#include <cuda_fp16.h>
#include <cstdint>

#define NG 4000      // genomes
#define NS 2048      // samples
#define NM 28000     // genes
#define NK 16000     // unique seqs
#define CAP 24       // max genes per seq bucket
#define HALF_S 1024  // sample half-width

// Scratch (allocation-free: __device__ globals; zero-initialized at load)
__device__ int    k_cnt[NK];                // bucket cursors (0 at entry & exit of every launch)
__device__ float2 k_slot[(size_t)NK * CAP]; // per-seq bucket: .x = genome idx (bits), .y = pos
__device__ __half Bh[(size_t)NG * NS];      // B in fp16, 16 MB

__device__ __forceinline__ float ex2f(float x) {
    float y;
    asm("ex2.approx.ftz.f32 %0, %1;" : "=f"(y) : "f"(x));
    return y;
}
__device__ __forceinline__ unsigned h2_as_u32(__half2 h) {
    union { __half2 h; unsigned u; } c; c.h = h; return c.u;
}
__device__ __forceinline__ float2 u32_as_f2h(unsigned u) {
    union { unsigned u; __half2 h; } c; c.u = u; return __half22float2(c.h);
}

struct f8 { float v[8]; };

// 32B A row load: non-coherent, pin in L2 (evict_last).
__device__ __forceinline__ f8 ldg_el8(const float* p) {
    unsigned r0, r1, r2, r3, r4, r5, r6, r7;
    asm("ld.global.nc.L2::evict_last.v8.b32 {%0,%1,%2,%3,%4,%5,%6,%7}, [%8];"
        : "=r"(r0), "=r"(r1), "=r"(r2), "=r"(r3),
          "=r"(r4), "=r"(r5), "=r"(r6), "=r"(r7) : "l"(p));
    f8 o;
    o.v[0] = __uint_as_float(r0); o.v[1] = __uint_as_float(r1);
    o.v[2] = __uint_as_float(r2); o.v[3] = __uint_as_float(r3);
    o.v[4] = __uint_as_float(r4); o.v[5] = __uint_as_float(r5);
    o.v[6] = __uint_as_float(r6); o.v[7] = __uint_as_float(r7);
    return o;
}

// 16B non-coherent load: 8 fp16 B samples.
__device__ __forceinline__ uint4 ldg_nc4(const void* p) {
    uint4 v;
    asm("ld.global.nc.v4.b32 {%0,%1,%2,%3}, [%4];"
        : "=r"(v.x), "=r"(v.y), "=r"(v.z), "=r"(v.w) : "l"(p));
    return v;
}

// Output stores: streaming (evict-first) so the 128MB stream never displaces A/Bh in L2.
__device__ __forceinline__ void stg_cs4(float* p, float a, float b, float c, float d) {
    asm volatile("st.global.cs.v4.f32 [%0], {%1,%2,%3,%4};"
                 :: "l"(p), "f"(a), "f"(b), "f"(c), "f"(d) : "memory");
}

// ---- Conversion kernel: one sample-half of B -> fp16 (compile-time half). ----
// DO_SCATTER=1 variant (lo half) also does the bucket scatter in its first NM threads.
template <int COL_BASE, int DO_SCATTER>
__global__ void __launch_bounds__(256)
conv_kernel(const float* __restrict__ B,
            const int* __restrict__ genome_idx, const int* __restrict__ seq_idx,
            const float* __restrict__ pos) {
    const int i = blockIdx.x * blockDim.x + threadIdx.x;   // 0 .. NG*HALF_S/8-1
    const int r = i >> 7;                                  // 128 threads per row-half
    const int c = ((i & 127) << 3) + COL_BASE;
    const size_t idx = (size_t)r * NS + c;
    const float4 x = __ldg(reinterpret_cast<const float4*>(B + idx));
    const float4 y = __ldg(reinterpret_cast<const float4*>(B + idx) + 1);
    uint4 packed;
    packed.x = h2_as_u32(__floats2half2_rn(x.x, x.y));
    packed.y = h2_as_u32(__floats2half2_rn(x.z, x.w));
    packed.z = h2_as_u32(__floats2half2_rn(y.x, y.y));
    packed.w = h2_as_u32(__floats2half2_rn(y.z, y.w));
    *reinterpret_cast<uint4*>(Bh + idx) = packed;

    if (DO_SCATTER && i < NM) {                            // bucket scatter (k_cnt: 0 -> cnt)
        int k = seq_idx[i];
        int cur = atomicAdd(&k_cnt[k], 1);
        if (cur < CAP) {
            float2 payload;
            payload.x = __int_as_float(genome_idx[i]);
            payload.y = pos[i];
            k_slot[(size_t)k * CAP + cur] = payload;
        }
    }
}

// ---- Main: seq-major fused gather over one sample half (A fp32 + B fp16). ----
// grid: NK CTAs; 128 threads; each owns 8 consecutive samples (128*8 == HALF_S).
// S_BASE/DO_RESET are compile-time to keep regs at 32 (runtime params cost 8 regs in R16).
template <int S_BASE, int DO_RESET>
__global__ void __launch_bounds__(128, 16)
main_kernel(const float* __restrict__ A, const float* __restrict__ bias,
            float* __restrict__ out) {
    const int k  = blockIdx.x;                  // output seq row
    const int s0 = S_BASE + threadIdx.x * 8;

    int cnt = k_cnt[k];
    if (cnt > CAP) cnt = CAP;
    const float2* slots = k_slot + (size_t)k * CAP;

    // G = A * 2^(1 - p*B) = 2 * A * 2^(-p*B): fold the 2 into bias.
    const float w = 2.0f * __ldg(bias + k);

    float acc[8];
#pragma unroll
    for (int j = 0; j < 8; j++) acc[j] = 0.f;

    // Software-pipelined slot payloads (proven in R13).
    float2 p0, p1;
    if (cnt > 0) p0 = slots[0];
    if (cnt > 1) p1 = slots[1];

    int i = 0;
    for (; i + 2 <= cnt; i += 2) {
        const float2 c0 = p0;
        const float2 c1 = p1;
        if (i + 3 < cnt) { p0 = slots[i + 2]; p1 = slots[i + 3]; }
        else if (i + 2 < cnt) { p0 = slots[i + 2]; }

        const size_t n0 = (size_t)__float_as_int(c0.x) * NS + s0;
        const size_t n1 = (size_t)__float_as_int(c1.x) * NS + s0;
        const f8   a0 = ldg_el8(A + n0);
        const uint4 h0 = ldg_nc4(Bh + n0);
        const f8   a1 = ldg_el8(A + n1);
        const uint4 h1 = ldg_nc4(Bh + n1);
        {
            const float2 b01 = u32_as_f2h(h0.x), b23 = u32_as_f2h(h0.y);
            const float2 b45 = u32_as_f2h(h0.z), b67 = u32_as_f2h(h0.w);
            acc[0] = fmaf(a0.v[0], ex2f(-c0.y * b01.x), acc[0]);
            acc[1] = fmaf(a0.v[1], ex2f(-c0.y * b01.y), acc[1]);
            acc[2] = fmaf(a0.v[2], ex2f(-c0.y * b23.x), acc[2]);
            acc[3] = fmaf(a0.v[3], ex2f(-c0.y * b23.y), acc[3]);
            acc[4] = fmaf(a0.v[4], ex2f(-c0.y * b45.x), acc[4]);
            acc[5] = fmaf(a0.v[5], ex2f(-c0.y * b45.y), acc[5]);
            acc[6] = fmaf(a0.v[6], ex2f(-c0.y * b67.x), acc[6]);
            acc[7] = fmaf(a0.v[7], ex2f(-c0.y * b67.y), acc[7]);
        }
        {
            const float2 b01 = u32_as_f2h(h1.x), b23 = u32_as_f2h(h1.y);
            const float2 b45 = u32_as_f2h(h1.z), b67 = u32_as_f2h(h1.w);
            acc[0] = fmaf(a1.v[0], ex2f(-c1.y * b01.x), acc[0]);
            acc[1] = fmaf(a1.v[1], ex2f(-c1.y * b01.y), acc[1]);
            acc[2] = fmaf(a1.v[2], ex2f(-c1.y * b23.x), acc[2]);
            acc[3] = fmaf(a1.v[3], ex2f(-c1.y * b23.y), acc[3]);
            acc[4] = fmaf(a1.v[4], ex2f(-c1.y * b45.x), acc[4]);
            acc[5] = fmaf(a1.v[5], ex2f(-c1.y * b45.y), acc[5]);
            acc[6] = fmaf(a1.v[6], ex2f(-c1.y * b67.x), acc[6]);
            acc[7] = fmaf(a1.v[7], ex2f(-c1.y * b67.y), acc[7]);
        }
    }
    if (i < cnt) {
        const size_t n0 = (size_t)__float_as_int(p0.x) * NS + s0;
        const f8   a0 = ldg_el8(A + n0);
        const uint4 h0 = ldg_nc4(Bh + n0);
        const float2 b01 = u32_as_f2h(h0.x), b23 = u32_as_f2h(h0.y);
        const float2 b45 = u32_as_f2h(h0.z), b67 = u32_as_f2h(h0.w);
        acc[0] = fmaf(a0.v[0], ex2f(-p0.y * b01.x), acc[0]);
        acc[1] = fmaf(a0.v[1], ex2f(-p0.y * b01.y), acc[1]);
        acc[2] = fmaf(a0.v[2], ex2f(-p0.y * b23.x), acc[2]);
        acc[3] = fmaf(a0.v[3], ex2f(-p0.y * b23.y), acc[3]);
        acc[4] = fmaf(a0.v[4], ex2f(-p0.y * b45.x), acc[4]);
        acc[5] = fmaf(a0.v[5], ex2f(-p0.y * b45.y), acc[5]);
        acc[6] = fmaf(a0.v[6], ex2f(-p0.y * b67.x), acc[6]);
        acc[7] = fmaf(a0.v[7], ex2f(-p0.y * b67.y), acc[7]);
    }

    float* po = out + (size_t)k * NS + s0;
    stg_cs4(po,     w * acc[0], w * acc[1], w * acc[2], w * acc[3]);
    stg_cs4(po + 4, w * acc[4], w * acc[5], w * acc[6], w * acc[7]);

    // Only the LAST consumer of k_cnt may reset it (main_hi).
    if (DO_RESET && threadIdx.x == 0) k_cnt[k] = 0;
}

// ---- Fork-join side stream (created once; streams/events are not device memory) ----
struct SideCtx {
    cudaStream_t s;
    cudaEvent_t  e_fork, e_join;
    SideCtx() {
        cudaStreamCreateWithFlags(&s, cudaStreamNonBlocking);
        cudaEventCreateWithFlags(&e_fork, cudaEventDisableTiming);
        cudaEventCreateWithFlags(&e_join, cudaEventDisableTiming);
    }
};
static SideCtx g_side;

// ---------------- launch ----------------
extern "C" void kernel_launch(void* const* d_in, const int* in_sizes, int n_in,
                              void* d_out, int out_size) {
    const float* A          = (const float*)d_in[0];   // (4000, 2048)
    const float* B          = (const float*)d_in[1];   // (4000, 2048)
    const float* bias       = (const float*)d_in[2];   // (16000,)
    const float* pos        = (const float*)d_in[3];   // (28000,)
    const int*   genome_idx = (const int*)d_in[4];     // (28000,)
    const int*   seq_idx    = (const int*)d_in[5];     // (28000,)
    float*       out        = (float*)d_out;           // (16000, 2048)

    const int conv_blocks = (NG * HALF_S / 8) / 256;   // 2000

    // 1. prep_lo: convert B[:, 0:1024) + bucket scatter.
    conv_kernel<0, 1><<<conv_blocks, 256>>>(B, genome_idx, seq_idx, pos);

    // 2. Fork: conv_hi on the side stream, ordered after prep_lo so it co-runs
    //    with main_lo (DRAM-bound conv under L2-bound main => real overlap).
    cudaEventRecord(g_side.e_fork, 0);
    cudaStreamWaitEvent(g_side.s, g_side.e_fork, 0);
    conv_kernel<HALF_S, 0><<<conv_blocks, 256, 0, g_side.s>>>(B, genome_idx, seq_idx, pos);
    cudaEventRecord(g_side.e_join, g_side.s);

    // 3. main_lo (samples 0-1023) on stream 0: needs only prep_lo's outputs.
    main_kernel<0, 0><<<NK, 128>>>(A, bias, out);

    // 4. Join, then main_hi (samples 1024-2047): needs conv_hi; resets k_cnt.
    cudaStreamWaitEvent(0, g_side.e_join, 0);
    main_kernel<HALF_S, 1><<<NK, 128>>>(A, bias, out);
}